// round 13
// baseline (speedup 1.0000x reference)
#include <cuda_runtime.h>
#include <cuda_bf16.h>
#include <math.h>

#define T_  12
#define M_  2048
#define B_  2
#define N_  1024
#define DIN 64
#define DH  128
#define DT  16
#define DO  32
#define NJC 8
#define CAPC 32

// tf32 helpers
__device__ __forceinline__ float cvt_tf32(float f) {
    unsigned r;
    asm("cvt.rna.tf32.f32 %0, %1;" : "=r"(r) : "f"(f));
    return __uint_as_float(r);
}
__device__ __forceinline__ float4 cvt_tf32_4(float4 v) {
    v.x = cvt_tf32(v.x); v.y = cvt_tf32(v.y);
    v.z = cvt_tf32(v.z); v.w = cvt_tf32(v.w);
    return v;
}
__device__ __forceinline__ void mma_tf32(float* c,
                                         unsigned a0, unsigned a1, unsigned a2, unsigned a3,
                                         unsigned b0, unsigned b1) {
    asm("mma.sync.aligned.m16n8k8.row.col.f32.tf32.tf32.f32 "
        "{%0,%1,%2,%3}, {%4,%5,%6,%7}, {%8,%9}, {%0,%1,%2,%3};"
        : "+f"(c[0]), "+f"(c[1]), "+f"(c[2]), "+f"(c[3])
        : "r"(a0), "r"(a1), "r"(a2), "r"(a3), "r"(b0), "r"(b1));
}

// ---------------- device scratch ---------------
__device__ int   g_mdtype;
__device__ int   g_mask[T_ * M_];
__device__ int   g_list[T_ * M_];
__device__ int   g_mcnt[T_];
__device__ int   g_cnt8[T_ * M_ * NJC];
__device__ int   g_col [T_ * M_ * NJC * CAPC];
__device__ float g_nrm [T_ * M_];
__device__ float g_z   [T_ * M_ * DH];
__device__ float g_h   [T_ * M_ * DH];
__device__ float g_Q   [T_ * M_ * DH];
__device__ float g_K   [T_ * M_ * DH];
__device__ float g_V   [T_ * M_ * DH];
__device__ float g_agg [T_ * M_ * DH];
__device__ float g_qt  [T_ * DH];
__device__ float g_kt  [T_ * DH];
__device__ float g_vt  [T_ * DH];
__device__ float g_wc  [DH * DO];
__device__ float g_bc  [DO];

// ---------------- mask dtype detection ----------------
__global__ void k_detect(const void* p) {
    const int*   wi = (const int*)p;
    const float* wf = (const float*)p;
    int oki = 1, okf = 1;
    for (int r = 0; r < 8; r++) {
        int idx = r * 256 + threadIdx.x;
        int w  = wi[idx];
        float f = wf[idx];
        oki &= (w == 0 || w == 1);
        okf &= (f == 0.0f || f == 1.0f);
    }
    oki = __syncthreads_and(oki);
    okf = __syncthreads_and(okf);
    if (threadIdx.x == 0) g_mdtype = okf ? 2 : (oki ? 1 : 0);
}

__global__ void k_mask(const void* em) {
    int idx = blockIdx.x * 256 + threadIdx.x;
    int t = idx >> 11, m = idx & (M_ - 1);
    int b = m >> 10, n = m & (N_ - 1);
    int src = (b * T_ + t) * N_ + n;
    int dt = g_mdtype;
    int v;
    if (dt == 1)      v = ((const int*)em)[src] != 0;
    else if (dt == 2) v = ((const float*)em)[src] != 0.0f;
    else              v = ((const unsigned char*)em)[src] != 0;
    g_mask[idx] = v;
}

__global__ void __launch_bounds__(1024) k_compact() {
    int t = blockIdx.x, tid = threadIdx.x;
    __shared__ int wsum[32];
    __shared__ int sbase;
    if (tid == 0) sbase = 0;
    __syncthreads();
    for (int half = 0; half < 2; half++) {
        int i = half * 1024 + tid;
        int mv = g_mask[t * M_ + i];
        unsigned b = __ballot_sync(0xffffffffu, mv);
        int lane = tid & 31, wid = tid >> 5;
        if (lane == 0) wsum[wid] = __popc(b);
        __syncthreads();
        int woff = 0;
        for (int w = 0; w < wid; w++) woff += wsum[w];
        if (mv) g_list[t * M_ + sbase + woff + __popc(b & ((1u << lane) - 1u))] = i;
        __syncthreads();
        if (tid == 0) {
            int tot = 0;
            for (int w = 0; w < 32; w++) tot += wsum[w];
            sbase += tot;
        }
        __syncthreads();
    }
    if (tid == 0) g_mcnt[t] = sbase;
}

// A scan over compacted masked-j list: dense loop, unconditional streaming loads
__global__ void k_edges(const float* __restrict__ A) {
    int t = blockIdx.x, jc = blockIdx.y, ic = blockIdx.z;
    int tid = threadIdx.x;
    int i = ic * 256 + tid;
    __shared__ int sj[256];
    __shared__ int wsum[8];
    __shared__ int scnt;
    int jbase = jc * 256;
    int lane = tid & 31, wid = tid >> 5;
    int mv = g_mask[t * M_ + jbase + tid];
    unsigned b = __ballot_sync(0xffffffffu, mv);
    if (lane == 0) wsum[wid] = __popc(b);
    __syncthreads();
    int woff = 0;
    for (int w = 0; w < wid; w++) woff += wsum[w];
    if (mv) sj[woff + __popc(b & ((1u << lane) - 1u))] = tid;
    if (tid == 0) {
        int tot = 0;
        for (int w = 0; w < 8; w++) tot += wsum[w];
        scnt = tot;
    }
    __syncthreads();
    int nj = scnt;
    int mi = g_mask[t * M_ + i];
    int cnt = 0;
    int* cols = g_col + ((size_t)((t * M_ + i) * NJC + jc)) * CAPC;
    if (mi) {
        const float* Ab = A + (size_t)(t * M_ + jbase) * M_ + i;
        int e = 0;
        for (; e + 8 <= nj; e += 8) {
            int j0 = sj[e], j1 = sj[e+1], j2 = sj[e+2], j3 = sj[e+3];
            int j4 = sj[e+4], j5 = sj[e+5], j6 = sj[e+6], j7 = sj[e+7];
            float a0 = Ab[(size_t)j0 * M_], a1 = Ab[(size_t)j1 * M_];
            float a2 = Ab[(size_t)j2 * M_], a3 = Ab[(size_t)j3 * M_];
            float a4 = Ab[(size_t)j4 * M_], a5 = Ab[(size_t)j5 * M_];
            float a6 = Ab[(size_t)j6 * M_], a7 = Ab[(size_t)j7 * M_];
            if (a0 != 0.0f && cnt < CAPC) cols[cnt++] = jbase + j0;
            if (a1 != 0.0f && cnt < CAPC) cols[cnt++] = jbase + j1;
            if (a2 != 0.0f && cnt < CAPC) cols[cnt++] = jbase + j2;
            if (a3 != 0.0f && cnt < CAPC) cols[cnt++] = jbase + j3;
            if (a4 != 0.0f && cnt < CAPC) cols[cnt++] = jbase + j4;
            if (a5 != 0.0f && cnt < CAPC) cols[cnt++] = jbase + j5;
            if (a6 != 0.0f && cnt < CAPC) cols[cnt++] = jbase + j6;
            if (a7 != 0.0f && cnt < CAPC) cols[cnt++] = jbase + j7;
        }
        for (; e < nj; e++) {
            int j = sj[e];
            float a = Ab[(size_t)j * M_];
            if (a != 0.0f && cnt < CAPC) cols[cnt++] = jbase + j;
        }
    }
    g_cnt8[(t * M_ + i) * NJC + jc] = cnt;
}

__global__ void k_nrm() {
    int idx = blockIdx.x * 256 + threadIdx.x;
    float nv = 0.0f;
    if (g_mask[idx]) {
        int c = 1;
        #pragma unroll
        for (int jc = 0; jc < NJC; jc++) c += g_cnt8[idx * NJC + jc];
        nv = rsqrtf((float)c);
    }
    g_nrm[idx] = nv;
}

__global__ void k_tbias(const float* __restrict__ tw, const float* __restrict__ tb,
                        const float* __restrict__ qw, const float* __restrict__ qb,
                        const float* __restrict__ kw, const float* __restrict__ kb,
                        const float* __restrict__ vw, const float* __restrict__ vb) {
    int t = blockIdx.x, f = threadIdx.x;
    float tv[DT];
    #pragma unroll
    for (int d = 0; d < DT; d++) tv[d] = sinf((float)t * tw[d] + tb[d]);
    float aq = qb[f], ak = kb[f], av = vb[f];
    #pragma unroll
    for (int d = 0; d < DT; d++) {
        aq += tv[d] * qw[(DH + d) * DH + f];
        ak += tv[d] * kw[(DH + d) * DH + f];
        av += tv[d] * vw[(DH + d) * DH + f];
    }
    g_qt[t * DH + f] = aq;
    g_kt[t * DH + f] = ak;
    g_vt[t * DH + f] = av;
}

__global__ void k_comb(const float* __restrict__ ow, const float* __restrict__ ob,
                       const float* __restrict__ fcw, const float* __restrict__ fcb) {
    int idx = blockIdx.x * 256 + threadIdx.x;
    int d = idx >> 5, f = idx & 31;
    float acc = 0.0f;
    #pragma unroll 8
    for (int e = 0; e < DH; e++) acc += ow[d * DH + e] * fcw[e * DO + f];
    g_wc[idx] = acc;
    if (idx < DO) {
        float b = fcb[idx];
        #pragma unroll 8
        for (int e = 0; e < DH; e++) b += ob[e] * fcw[e * DO + idx];
        g_bc[idx] = b;
    }
}

// ============ tf32 mma GEMM: 64 nodes x 128 features ============
#define WSTR 136
__global__ void __launch_bounds__(256) k_gemm_z(const float* __restrict__ xsrc,
                                                const float* __restrict__ W, int mode) {
    int t = blockIdx.x;
    int mc = g_mcnt[t];
    int mbase = blockIdx.y * 64;
    if (mbase >= mc) return;
    const float* src = (mode == 0) ? xsrc : (const float*)g_h;
    const int K = (mode == 0) ? DIN : DH;

    __shared__ float As[64][36];
    __shared__ float Ws[32][WSTR];
    __shared__ int   ridx[64];
    __shared__ float rn[64];
    int tid = threadIdx.x;
    if (tid < 64) {
        int lp = mbase + tid;
        int i = g_list[t * M_ + (lp < mc ? lp : mc - 1)];
        ridx[tid] = i;
        rn[tid] = g_nrm[t * M_ + i];
    }
    int w = tid >> 5, lane = tid & 31;
    int gID = lane >> 2, tig = lane & 3;
    int mq = (w & 3) * 16, nh = (w >> 2) * 64;

    float o[8][4];
    #pragma unroll
    for (int i = 0; i < 8; i++)
        #pragma unroll
        for (int j = 0; j < 4; j++) o[i][j] = 0.0f;

    for (int k0 = 0; k0 < K; k0 += 32) {
        __syncthreads();
        {
            int m = tid >> 3;
            int kk = (tid & 7) * 4;
            #pragma unroll
            for (int p = 0; p < 2; p++) {
                int mm = m + p * 32;
                float4 v = cvt_tf32_4(*(const float4*)(src + (size_t)(t * M_ + ridx[mm]) * K + k0 + kk));
                *(float4*)&As[mm][kk] = v;
            }
        }
        {
            #pragma unroll
            for (int p = 0; p < 4; p++) {
                int idx4 = tid + p * 256;
                int row = idx4 >> 5, c4 = (idx4 & 31) * 4;
                float4 v = cvt_tf32_4(*(const float4*)(W + (size_t)(k0 + row) * DH + c4));
                *(float4*)&Ws[row][c4] = v;
            }
        }
        __syncthreads();
        #pragma unroll
        for (int s = 0; s < 4; s++) {
            int kk = s * 8;
            unsigned a0 = __float_as_uint(As[mq + gID][kk + tig]);
            unsigned a1 = __float_as_uint(As[mq + gID + 8][kk + tig]);
            unsigned a2 = __float_as_uint(As[mq + gID][kk + tig + 4]);
            unsigned a3 = __float_as_uint(As[mq + gID + 8][kk + tig + 4]);
            #pragma unroll
            for (int ns = 0; ns < 8; ns++) {
                int col = nh + ns * 8 + gID;
                unsigned b0 = __float_as_uint(Ws[kk + tig][col]);
                unsigned b1 = __float_as_uint(Ws[kk + tig + 4][col]);
                mma_tf32(o[ns], a0, a1, a2, a3, b0, b1);
            }
        }
    }
    int r0 = mq + gID, r1 = r0 + 8;
    if (mbase + r0 < mc) {
        float s = rn[r0];
        float* dst = g_z + (size_t)(t * M_ + ridx[r0]) * DH + nh;
        #pragma unroll
        for (int ns = 0; ns < 8; ns++) {
            float2 v = {o[ns][0] * s, o[ns][1] * s};
            *(float2*)(dst + ns * 8 + 2 * tig) = v;
        }
    }
    if (mbase + r1 < mc) {
        float s = rn[r1];
        float* dst = g_z + (size_t)(t * M_ + ridx[r1]) * DH + nh;
        #pragma unroll
        for (int ns = 0; ns < 8; ns++) {
            float2 v = {o[ns][2] * s, o[ns][3] * s};
            *(float2*)(dst + ns * 8 + 2 * tig) = v;
        }
    }
}

// QKV GEMM via tf32 mma
__global__ void __launch_bounds__(256) k_gemm_qkv(const float* __restrict__ qw,
                                                  const float* __restrict__ kw,
                                                  const float* __restrict__ vw) {
    int t = blockIdx.x;
    int mc = g_mcnt[t];
    int mbase = blockIdx.y * 64;
    if (mbase >= mc) return;
    int sel = blockIdx.z;
    const float* W  = (sel == 0) ? qw : (sel == 1) ? kw : vw;
    const float* tb = (sel == 0) ? g_qt : (sel == 1) ? g_kt : g_vt;
    float* out      = (sel == 0) ? g_Q : (sel == 1) ? g_K : g_V;

    __shared__ float As[64][36];
    __shared__ float Ws[32][WSTR];
    __shared__ int   ridx[64];
    int tid = threadIdx.x;
    if (tid < 64) {
        int lp = mbase + tid;
        ridx[tid] = g_list[t * M_ + (lp < mc ? lp : mc - 1)];
    }
    int w = tid >> 5, lane = tid & 31;
    int gID = lane >> 2, tig = lane & 3;
    int mq = (w & 3) * 16, nh = (w >> 2) * 64;

    float o[8][4];
    #pragma unroll
    for (int i = 0; i < 8; i++)
        #pragma unroll
        for (int j = 0; j < 4; j++) o[i][j] = 0.0f;

    for (int k0 = 0; k0 < DH; k0 += 32) {
        __syncthreads();
        {
            int m = tid >> 3;
            int kk = (tid & 7) * 4;
            #pragma unroll
            for (int p = 0; p < 2; p++) {
                int mm = m + p * 32;
                float4 v = cvt_tf32_4(*(const float4*)(g_h + (size_t)(t * M_ + ridx[mm]) * DH + k0 + kk));
                *(float4*)&As[mm][kk] = v;
            }
        }
        {
            #pragma unroll
            for (int p = 0; p < 4; p++) {
                int idx4 = tid + p * 256;
                int row = idx4 >> 5, c4 = (idx4 & 31) * 4;
                float4 v = cvt_tf32_4(*(const float4*)(W + (size_t)(k0 + row) * DH + c4));
                *(float4*)&Ws[row][c4] = v;
            }
        }
        __syncthreads();
        #pragma unroll
        for (int s = 0; s < 4; s++) {
            int kk = s * 8;
            unsigned a0 = __float_as_uint(As[mq + gID][kk + tig]);
            unsigned a1 = __float_as_uint(As[mq + gID + 8][kk + tig]);
            unsigned a2 = __float_as_uint(As[mq + gID][kk + tig + 4]);
            unsigned a3 = __float_as_uint(As[mq + gID + 8][kk + tig + 4]);
            #pragma unroll
            for (int ns = 0; ns < 8; ns++) {
                int col = nh + ns * 8 + gID;
                unsigned b0 = __float_as_uint(Ws[kk + tig][col]);
                unsigned b1 = __float_as_uint(Ws[kk + tig + 4][col]);
                mma_tf32(o[ns], a0, a1, a2, a3, b0, b1);
            }
        }
    }
    int r0 = mq + gID, r1 = r0 + 8;
    if (mbase + r0 < mc) {
        float* dst = out + (size_t)(t * M_ + mbase + r0) * DH + nh;
        #pragma unroll
        for (int ns = 0; ns < 8; ns++) {
            int c = ns * 8 + 2 * tig;
            float2 bv = *(const float2*)(tb + t * DH + nh + c);
            float2 v = {o[ns][0] + bv.x, o[ns][1] + bv.y};
            *(float2*)(dst + c) = v;
        }
    }
    if (mbase + r1 < mc) {
        float* dst = out + (size_t)(t * M_ + mbase + r1) * DH + nh;
        #pragma unroll
        for (int ns = 0; ns < 8; ns++) {
            int c = ns * 8 + 2 * tig;
            float2 bv = *(const float2*)(tb + t * DH + nh + c);
            float2 v = {o[ns][2] + bv.x, o[ns][3] + bv.y};
            *(float2*)(dst + c) = v;
        }
    }
}

__global__ void __launch_bounds__(256) k_out2(float* __restrict__ out) {
    int t = blockIdx.x;
    int mc = g_mcnt[t];
    int mbase = blockIdx.y * 64;
    if (mbase >= mc) return;
    __shared__ float As[64][36];
    __shared__ float Ws2[32][DO];
    __shared__ int   ridx[64];
    int tid = threadIdx.x;
    if (tid < 64) {
        int lp = mbase + tid;
        ridx[tid] = g_list[t * M_ + (lp < mc ? lp : mc - 1)];
    }
    float acc[4][2];
    #pragma unroll
    for (int i = 0; i < 4; i++) { acc[i][0] = 0.0f; acc[i][1] = 0.0f; }
    int ty = tid >> 4, tx = tid & 15;
    int m0 = ty * 4, n0 = tx * 2;

    for (int k0 = 0; k0 < DH; k0 += 32) {
        __syncthreads();
        {
            int m = tid >> 3;
            int kk = (tid & 7) * 4;
            #pragma unroll
            for (int p = 0; p < 2; p++) {
                int mm = m + p * 32;
                int lp = mbase + mm;
                int lpc = (lp < mc ? lp : mc - 1);
                float4 v = *(const float4*)(g_agg + (size_t)(t * M_ + lpc) * DH + k0 + kk);
                As[mm][kk] = v.x; As[mm][kk + 1] = v.y; As[mm][kk + 2] = v.z; As[mm][kk + 3] = v.w;
            }
        }
        {
            float4* Ws4 = (float4*)Ws2;
            const float4* W4 = (const float4*)(g_wc + (size_t)k0 * DO);
            Ws4[tid] = W4[tid];
        }
        __syncthreads();
        #pragma unroll
        for (int kk = 0; kk < 32; kk++) {
            float a0 = As[m0][kk], a1 = As[m0 + 1][kk], a2 = As[m0 + 2][kk], a3 = As[m0 + 3][kk];
            float2 b = *(float2*)&Ws2[kk][n0];
            acc[0][0] += a0 * b.x; acc[0][1] += a0 * b.y;
            acc[1][0] += a1 * b.x; acc[1][1] += a1 * b.y;
            acc[2][0] += a2 * b.x; acc[2][1] += a2 * b.y;
            acc[3][0] += a3 * b.x; acc[3][1] += a3 * b.y;
        }
    }
    float2 bc = *(const float2*)(g_bc + n0);
    #pragma unroll
    for (int i = 0; i < 4; i++) {
        int lp = mbase + m0 + i;
        if (lp < mc) {
            int node = ridx[m0 + i];
            float2 o = {acc[i][0] + bc.x, acc[i][1] + bc.y};
            *(float2*)(out + ((size_t)node * T_ + t) * DO + n0) = o;
        }
    }
}

// ---------------- sparse aggregation + bias + ReLU ----------------
__global__ void k_spmm(const float* __restrict__ bias) {
    int t = blockIdx.x, lp = blockIdx.y;
    if (lp >= g_mcnt[t]) return;
    int i = g_list[t * M_ + lp];
    int f = threadIdx.x;
    float acc = g_z[(size_t)(t * M_ + i) * DH + f];
    const int* c8 = g_cnt8 + (t * M_ + i) * NJC;
    #pragma unroll
    for (int jc = 0; jc < NJC; jc++) {
        int c = c8[jc];
        const int* cl = g_col + ((size_t)((t * M_ + i) * NJC + jc)) * CAPC;
        for (int e = 0; e < c; e++) {
            int j = cl[e];
            acc += g_z[(size_t)(t * M_ + j) * DH + f];
        }
    }
    g_h[(size_t)(t * M_ + i) * DH + f] =
        fmaxf(g_nrm[t * M_ + i] * acc + bias[f], 0.0f);
}

// ---------------- flash attention: QT=128, m=32 warp tiles, tf32 mma ----------------
#define QT 128
#define KC 64
#define QSTR 132      // ≡4 mod 32 — A-frag loads conflict-free
#define KSTR 132      // ≡4 — QK B-frag conflict-free
#define VSTR 136      // ≡8 — PV B-frag conflict-free
#define SSTR 68       // ≡4
extern __shared__ float smattn[];
__global__ void __launch_bounds__(256, 1) k_attn() {
    int t = blockIdx.x;
    int mc = g_mcnt[t];
    int qb = blockIdx.y * QT;
    if (qb >= mc) return;
    float* Qs   = smattn;                 // QT*QSTR
    float* Ks   = Qs + QT * QSTR;         // KC*VSTR buffer (K: stride KSTR, V: stride VSTR)
    float* S    = Ks + KC * VSTR;         // QT*SSTR
    float* rowm = S + QT * SSTR;          // QT
    float* rowl = rowm + QT;
    float* rowsc= rowl + QT;
    int tid = threadIdx.x;
    int w = tid >> 5, lane = tid & 31;
    int gID = lane >> 2, tig = lane & 3;
    int mq = (w & 3) * 32;                // 32-row q tile per warp
    int dh = w >> 2;                      // d-half
    int nv = min(QT, mc - qb);
    const float scl = 0.08838834764831845f;

    // Q fill: QT*DH/4 = 4096 float4
    for (int p = 0; p < 16; p++) {
        int idx4 = tid + p * 256;
        int q = idx4 >> 5, d4 = (idx4 & 31) * 4;
        float4 v = {0.f, 0.f, 0.f, 0.f};
        if (q < nv) v = cvt_tf32_4(*(const float4*)(g_Q + (size_t)(t * M_ + qb + q) * DH + d4));
        *(float4*)(Qs + q * QSTR + d4) = v;
    }
    if (tid < QT) { rowm[tid] = -1e30f; rowl[tid] = 0.0f; }

    float o[2][8][4];                     // 2 m16-subtiles x 8 ns
    #pragma unroll
    for (int mi = 0; mi < 2; mi++)
        #pragma unroll
        for (int i = 0; i < 8; i++)
            #pragma unroll
            for (int j = 0; j < 4; j++) o[mi][i][j] = 0.0f;

    for (int kb = 0; kb < mc; kb += KC) {
        int kn = min(KC, mc - kb);
        __syncthreads();
        // K fill
        for (int p = 0; p < 8; p++) {
            int idx4 = tid + p * 256;
            int k = idx4 >> 5, d4 = (idx4 & 31) * 4;
            float4 v = {0.f, 0.f, 0.f, 0.f};
            if (k < kn) v = cvt_tf32_4(*(const float4*)(g_K + (size_t)(t * M_ + kb + k) * DH + d4));
            *(float4*)(Ks + k * KSTR + d4) = v;
        }
        __syncthreads();
        // QK scores: warp tile 32q x 64k over d-half
        float c[2][8][4];
        #pragma unroll
        for (int mi = 0; mi < 2; mi++)
            #pragma unroll
            for (int i = 0; i < 8; i++)
                #pragma unroll
                for (int j = 0; j < 4; j++) c[mi][i][j] = 0.0f;
        {
            int dbase = dh * 64;
            #pragma unroll
            for (int s = 0; s < 8; s++) {
                int d0 = dbase + s * 8;
                unsigned a00 = __float_as_uint(Qs[(mq + gID) * QSTR + d0 + tig]);
                unsigned a01 = __float_as_uint(Qs[(mq + gID + 8) * QSTR + d0 + tig]);
                unsigned a02 = __float_as_uint(Qs[(mq + gID) * QSTR + d0 + tig + 4]);
                unsigned a03 = __float_as_uint(Qs[(mq + gID + 8) * QSTR + d0 + tig + 4]);
                unsigned a10 = __float_as_uint(Qs[(mq + 16 + gID) * QSTR + d0 + tig]);
                unsigned a11 = __float_as_uint(Qs[(mq + 24 + gID) * QSTR + d0 + tig]);
                unsigned a12 = __float_as_uint(Qs[(mq + 16 + gID) * QSTR + d0 + tig + 4]);
                unsigned a13 = __float_as_uint(Qs[(mq + 24 + gID) * QSTR + d0 + tig + 4]);
                #pragma unroll
                for (int ns = 0; ns < 8; ns++) {
                    unsigned b0 = __float_as_uint(Ks[(ns * 8 + gID) * KSTR + d0 + tig]);
                    unsigned b1 = __float_as_uint(Ks[(ns * 8 + gID) * KSTR + d0 + tig + 4]);
                    mma_tf32(c[0][ns], a00, a01, a02, a03, b0, b1);
                    mma_tf32(c[1][ns], a10, a11, a12, a13, b0, b1);
                }
            }
        }
        // combine d-halves deterministically: dh0 writes, dh1 adds+scales+masks
        if (dh == 0) {
            #pragma unroll
            for (int mi = 0; mi < 2; mi++) {
                int rb = mq + mi * 16 + gID;
                #pragma unroll
                for (int ns = 0; ns < 8; ns++) {
                    int col = ns * 8 + 2 * tig;
                    S[rb * SSTR + col]     = c[mi][ns][0];
                    S[rb * SSTR + col + 1] = c[mi][ns][1];
                    S[(rb + 8) * SSTR + col]     = c[mi][ns][2];
                    S[(rb + 8) * SSTR + col + 1] = c[mi][ns][3];
                }
            }
        }
        __syncthreads();
        if (dh == 1) {
            #pragma unroll
            for (int mi = 0; mi < 2; mi++) {
                int rb = mq + mi * 16 + gID;
                #pragma unroll
                for (int ns = 0; ns < 8; ns++) {
                    int col = ns * 8 + 2 * tig;
                    int r0 = rb * SSTR, r1 = (rb + 8) * SSTR;
                    S[r0 + col]     = (col     < kn) ? (S[r0 + col]     + c[mi][ns][0]) * scl : -1e30f;
                    S[r0 + col + 1] = (col + 1 < kn) ? (S[r0 + col + 1] + c[mi][ns][1]) * scl : -1e30f;
                    S[r1 + col]     = (col     < kn) ? (S[r1 + col]     + c[mi][ns][2]) * scl : -1e30f;
                    S[r1 + col + 1] = (col + 1 < kn) ? (S[r1 + col + 1] + c[mi][ns][3]) * scl : -1e30f;
                }
            }
        }
        __syncthreads();
        // online softmax: 8 warps x 16 rows, 2 lanes per row
        {
            int row = w * 16 + (lane >> 1);
            int l2 = lane & 1;
            float* Sr = S + row * SSTR;
            float mloc = -1e30f;
            for (int k = l2; k < KC; k += 2) mloc = fmaxf(mloc, Sr[k]);
            mloc = fmaxf(mloc, __shfl_xor_sync(0xffffffffu, mloc, 1));
            float oldm = rowm[row];
            float newm = fmaxf(oldm, mloc);
            float ssum = 0.0f;
            for (int k = l2; k < KC; k += 2) {
                float p = cvt_tf32(__expf(Sr[k] - newm));
                Sr[k] = p;
                ssum += p;
            }
            ssum += __shfl_xor_sync(0xffffffffu, ssum, 1);
            if (l2 == 0) {
                float sc = __expf(oldm - newm);
                rowsc[row] = sc;
                rowl[row] = rowl[row] * sc + ssum;
                rowm[row] = newm;
            }
        }
        __syncthreads();
        // rescale PV accumulators
        {
            #pragma unroll
            for (int mi = 0; mi < 2; mi++) {
                float sc0 = rowsc[mq + mi * 16 + gID];
                float sc1 = rowsc[mq + mi * 16 + gID + 8];
                #pragma unroll
                for (int ns = 0; ns < 8; ns++) {
                    o[mi][ns][0] *= sc0; o[mi][ns][1] *= sc0;
                    o[mi][ns][2] *= sc1; o[mi][ns][3] *= sc1;
                }
            }
        }
        // V fill (stride VSTR)
        for (int p = 0; p < 8; p++) {
            int idx4 = tid + p * 256;
            int k = idx4 >> 5, d4 = (idx4 & 31) * 4;
            float4 v = {0.f, 0.f, 0.f, 0.f};
            if (k < kn) v = cvt_tf32_4(*(const float4*)(g_V + (size_t)(t * M_ + kb + k) * DH + d4));
            *(float4*)(Ks + k * VSTR + d4) = v;
        }
        __syncthreads();
        // PV: warp tile 32q x 64d (d-half)
        {
            int dbase = dh * 64;
            #pragma unroll
            for (int s = 0; s < 8; s++) {
                int k0 = s * 8;
                unsigned a00 = __float_as_uint(S[(mq + gID) * SSTR + k0 + tig]);
                unsigned a01 = __float_as_uint(S[(mq + gID + 8) * SSTR + k0 + tig]);
                unsigned a02 = __float_as_uint(S[(mq + gID) * SSTR + k0 + tig + 4]);
                unsigned a03 = __float_as_uint(S[(mq + gID + 8) * SSTR + k0 + tig + 4]);
                unsigned a10 = __float_as_uint(S[(mq + 16 + gID) * SSTR + k0 + tig]);
                unsigned a11 = __float_as_uint(S[(mq + 24 + gID) * SSTR + k0 + tig]);
                unsigned a12 = __float_as_uint(S[(mq + 16 + gID) * SSTR + k0 + tig + 4]);
                unsigned a13 = __float_as_uint(S[(mq + 24 + gID) * SSTR + k0 + tig + 4]);
                #pragma unroll
                for (int ns = 0; ns < 8; ns++) {
                    int col = dbase + ns * 8 + gID;
                    unsigned b0 = __float_as_uint(Ks[(k0 + tig) * VSTR + col]);
                    unsigned b1 = __float_as_uint(Ks[(k0 + tig + 4) * VSTR + col]);
                    mma_tf32(o[0][ns], a00, a01, a02, a03, b0, b1);
                    mma_tf32(o[1][ns], a10, a11, a12, a13, b0, b1);
                }
            }
        }
    }
    __syncthreads();
    // final normalize + store
    {
        int dbase = dh * 64;
        #pragma unroll
        for (int mi = 0; mi < 2; mi++) {
            int r0 = mq + mi * 16 + gID, r1 = r0 + 8;
            if (r0 < nv) {
                float inv = 1.0f / rowl[r0];
                float* dst = g_agg + (size_t)(t * M_ + qb + r0) * DH + dbase;
                #pragma unroll
                for (int ns = 0; ns < 8; ns++) {
                    float2 v = {o[mi][ns][0] * inv, o[mi][ns][1] * inv};
                    *(float2*)(dst + ns * 8 + 2 * tig) = v;
                }
            }
            if (r1 < nv) {
                float inv = 1.0f / rowl[r1];
                float* dst = g_agg + (size_t)(t * M_ + qb + r1) * DH + dbase;
                #pragma unroll
                for (int ns = 0; ns < 8; ns++) {
                    float2 v = {o[mi][ns][2] * inv, o[mi][ns][3] * inv};
                    *(float2*)(dst + ns * 8 + 2 * tig) = v;
                }
            }
        }
    }
}

// ---------------- launch ----------------
extern "C" void kernel_launch(void* const* d_in, const int* in_sizes, int n_in,
                              void* d_out, int out_size) {
    const float* x   = (const float*)d_in[0];
    const float* A   = (const float*)d_in[1];
    const void*  em  = d_in[2];
    const float* w1  = (const float*)d_in[3];
    const float* b1  = (const float*)d_in[4];
    const float* w2  = (const float*)d_in[5];
    const float* b2  = (const float*)d_in[6];
    const float* tw  = (const float*)d_in[7];
    const float* tb  = (const float*)d_in[8];
    const float* qw  = (const float*)d_in[9];
    const float* qb  = (const float*)d_in[10];
    const float* kw  = (const float*)d_in[11];
    const float* kb  = (const float*)d_in[12];
    const float* vw  = (const float*)d_in[13];
    const float* vb  = (const float*)d_in[14];
    const float* ow  = (const float*)d_in[15];
    const float* ob  = (const float*)d_in[16];
    const float* fcw = (const float*)d_in[17];
    const float* fcb = (const float*)d_in[18];

    const int ATTN_SMEM = (QT * QSTR + KC * VSTR + QT * SSTR + 3 * QT) * 4; // 138752 B
    cudaFuncSetAttribute(k_attn, cudaFuncAttributeMaxDynamicSharedMemorySize, ATTN_SMEM);

    k_detect<<<1, 256>>>(em);
    k_mask<<<(T_ * M_) / 256, 256>>>(em);
    k_compact<<<T_, 1024>>>();
    k_edges<<<dim3(T_, NJC, M_ / 256), 256>>>(A);
    k_nrm<<<(T_ * M_) / 256, 256>>>();
    k_tbias<<<T_, DH>>>(tw, tb, qw, qb, kw, kb, vw, vb);
    k_comb<<<16, 256>>>(ow, ob, fcw, fcb);
    k_gemm_z<<<dim3(T_, M_ / 64), 256>>>(x, w1, 0);
    k_spmm<<<dim3(T_, M_), DH>>>(b1);
    k_gemm_z<<<dim3(T_, M_ / 64), 256>>>(nullptr, w2, 1);
    k_spmm<<<dim3(T_, M_), DH>>>(b2);
    k_gemm_qkv<<<dim3(T_, M_ / 64, 3), 256>>>(qw, kw, vw);
    k_attn<<<dim3(T_, M_ / QT), 256, ATTN_SMEM>>>();
    cudaMemsetAsync(d_out, 0, (size_t)out_size * sizeof(float));
    k_out2<<<dim3(T_, M_ / 64), 256>>>((float*)d_out);
}

// round 14
// speedup vs baseline: 1.5290x; 1.5290x over previous
#include <cuda_runtime.h>
#include <cuda_bf16.h>
#include <math.h>

#define T_  12
#define M_  2048
#define B_  2
#define N_  1024
#define DIN 64
#define DH  128
#define DT  16
#define DO  32
#define NJC 8
#define CAPC 32

// tf32 helpers
__device__ __forceinline__ float cvt_tf32(float f) {
    unsigned r;
    asm("cvt.rna.tf32.f32 %0, %1;" : "=r"(r) : "f"(f));
    return __uint_as_float(r);
}
__device__ __forceinline__ float4 cvt_tf32_4(float4 v) {
    v.x = cvt_tf32(v.x); v.y = cvt_tf32(v.y);
    v.z = cvt_tf32(v.z); v.w = cvt_tf32(v.w);
    return v;
}
__device__ __forceinline__ void mma_tf32(float* c,
                                         unsigned a0, unsigned a1, unsigned a2, unsigned a3,
                                         unsigned b0, unsigned b1) {
    asm("mma.sync.aligned.m16n8k8.row.col.f32.tf32.tf32.f32 "
        "{%0,%1,%2,%3}, {%4,%5,%6,%7}, {%8,%9}, {%0,%1,%2,%3};"
        : "+f"(c[0]), "+f"(c[1]), "+f"(c[2]), "+f"(c[3])
        : "r"(a0), "r"(a1), "r"(a2), "r"(a3), "r"(b0), "r"(b1));
}

// ---------------- device scratch ---------------
__device__ int   g_mdtype;
__device__ int   g_mask[T_ * M_];
__device__ int   g_list[T_ * M_];
__device__ int   g_mcnt[T_];
__device__ int   g_cnt8[T_ * M_ * NJC];
__device__ int   g_col [T_ * M_ * NJC * CAPC];
__device__ float g_nrm [T_ * M_];
__device__ float g_z   [T_ * M_ * DH];
__device__ float g_h   [T_ * M_ * DH];
__device__ float g_Q   [T_ * M_ * DH];
__device__ float g_K   [T_ * M_ * DH];
__device__ float g_V   [T_ * M_ * DH];
__device__ float g_agg [T_ * M_ * DH];
__device__ float g_qt  [T_ * DH];
__device__ float g_kt  [T_ * DH];
__device__ float g_vt  [T_ * DH];
__device__ float g_wc  [DH * DO];
__device__ float g_bc  [DO];

// ---------------- mask dtype detection ----------------
__global__ void k_detect(const void* p) {
    const int*   wi = (const int*)p;
    const float* wf = (const float*)p;
    int oki = 1, okf = 1;
    for (int r = 0; r < 8; r++) {
        int idx = r * 256 + threadIdx.x;
        int w  = wi[idx];
        float f = wf[idx];
        oki &= (w == 0 || w == 1);
        okf &= (f == 0.0f || f == 1.0f);
    }
    oki = __syncthreads_and(oki);
    okf = __syncthreads_and(okf);
    if (threadIdx.x == 0) g_mdtype = okf ? 2 : (oki ? 1 : 0);
}

__global__ void k_mask(const void* em) {
    int idx = blockIdx.x * 256 + threadIdx.x;
    int t = idx >> 11, m = idx & (M_ - 1);
    int b = m >> 10, n = m & (N_ - 1);
    int src = (b * T_ + t) * N_ + n;
    int dt = g_mdtype;
    int v;
    if (dt == 1)      v = ((const int*)em)[src] != 0;
    else if (dt == 2) v = ((const float*)em)[src] != 0.0f;
    else              v = ((const unsigned char*)em)[src] != 0;
    g_mask[idx] = v;
}

__global__ void __launch_bounds__(1024) k_compact() {
    int t = blockIdx.x, tid = threadIdx.x;
    __shared__ int wsum[32];
    __shared__ int sbase;
    if (tid == 0) sbase = 0;
    __syncthreads();
    for (int half = 0; half < 2; half++) {
        int i = half * 1024 + tid;
        int mv = g_mask[t * M_ + i];
        unsigned b = __ballot_sync(0xffffffffu, mv);
        int lane = tid & 31, wid = tid >> 5;
        if (lane == 0) wsum[wid] = __popc(b);
        __syncthreads();
        int woff = 0;
        for (int w = 0; w < wid; w++) woff += wsum[w];
        if (mv) g_list[t * M_ + sbase + woff + __popc(b & ((1u << lane) - 1u))] = i;
        __syncthreads();
        if (tid == 0) {
            int tot = 0;
            for (int w = 0; w < 32; w++) tot += wsum[w];
            sbase += tot;
        }
        __syncthreads();
    }
    if (tid == 0) g_mcnt[t] = sbase;
}

// streaming A scan (unconditional loads keep MLP high)
__global__ void k_edges(const float* __restrict__ A) {
    int t = blockIdx.x, jc = blockIdx.y, ic = blockIdx.z;
    int i = ic * 256 + threadIdx.x;
    __shared__ int mj[256];
    int jbase = jc * 256;
    mj[threadIdx.x] = g_mask[t * M_ + jbase + threadIdx.x];
    __syncthreads();
    int mi = g_mask[t * M_ + i];
    int cnt = 0;
    int* cols = g_col + ((size_t)((t * M_ + i) * NJC + jc)) * CAPC;
    if (mi) {
        const float* Ab = A + (size_t)(t * M_ + jbase) * M_ + i;
        #pragma unroll 8
        for (int jj = 0; jj < 256; jj++) {
            float a = Ab[(size_t)jj * M_];
            if (a != 0.0f && mj[jj] && cnt < CAPC) cols[cnt++] = jbase + jj;
        }
    }
    g_cnt8[(t * M_ + i) * NJC + jc] = cnt;
}

__global__ void k_nrm() {
    int idx = blockIdx.x * 256 + threadIdx.x;
    float nv = 0.0f;
    if (g_mask[idx]) {
        int c = 1;
        #pragma unroll
        for (int jc = 0; jc < NJC; jc++) c += g_cnt8[idx * NJC + jc];
        nv = rsqrtf((float)c);
    }
    g_nrm[idx] = nv;
}

__global__ void k_tbias(const float* __restrict__ tw, const float* __restrict__ tb,
                        const float* __restrict__ qw, const float* __restrict__ qb,
                        const float* __restrict__ kw, const float* __restrict__ kb,
                        const float* __restrict__ vw, const float* __restrict__ vb) {
    int t = blockIdx.x, f = threadIdx.x;
    float tv[DT];
    #pragma unroll
    for (int d = 0; d < DT; d++) tv[d] = sinf((float)t * tw[d] + tb[d]);
    float aq = qb[f], ak = kb[f], av = vb[f];
    #pragma unroll
    for (int d = 0; d < DT; d++) {
        aq += tv[d] * qw[(DH + d) * DH + f];
        ak += tv[d] * kw[(DH + d) * DH + f];
        av += tv[d] * vw[(DH + d) * DH + f];
    }
    g_qt[t * DH + f] = aq;
    g_kt[t * DH + f] = ak;
    g_vt[t * DH + f] = av;
}

__global__ void k_comb(const float* __restrict__ ow, const float* __restrict__ ob,
                       const float* __restrict__ fcw, const float* __restrict__ fcb) {
    int idx = blockIdx.x * 256 + threadIdx.x;
    int d = idx >> 5, f = idx & 31;
    float acc = 0.0f;
    #pragma unroll 8
    for (int e = 0; e < DH; e++) acc += ow[d * DH + e] * fcw[e * DO + f];
    g_wc[idx] = acc;
    if (idx < DO) {
        float b = fcb[idx];
        #pragma unroll 8
        for (int e = 0; e < DH; e++) b += ob[e] * fcw[e * DO + idx];
        g_bc[idx] = b;
    }
}

// ============ tf32 mma GEMM: 64 nodes x 128 features ============
#define WSTR 136
__global__ void __launch_bounds__(256) k_gemm_z(const float* __restrict__ xsrc,
                                                const float* __restrict__ W, int mode) {
    int t = blockIdx.x;
    int mc = g_mcnt[t];
    int mbase = blockIdx.y * 64;
    if (mbase >= mc) return;
    const float* src = (mode == 0) ? xsrc : (const float*)g_h;
    const int K = (mode == 0) ? DIN : DH;

    __shared__ float As[64][36];
    __shared__ float Ws[32][WSTR];
    __shared__ int   ridx[64];
    __shared__ float rn[64];
    int tid = threadIdx.x;
    if (tid < 64) {
        int lp = mbase + tid;
        int i = g_list[t * M_ + (lp < mc ? lp : mc - 1)];
        ridx[tid] = i;
        rn[tid] = g_nrm[t * M_ + i];
    }
    int w = tid >> 5, lane = tid & 31;
    int gID = lane >> 2, tig = lane & 3;
    int mq = (w & 3) * 16, nh = (w >> 2) * 64;

    float o[8][4];
    #pragma unroll
    for (int i = 0; i < 8; i++)
        #pragma unroll
        for (int j = 0; j < 4; j++) o[i][j] = 0.0f;

    for (int k0 = 0; k0 < K; k0 += 32) {
        __syncthreads();
        {
            int m = tid >> 3;
            int kk = (tid & 7) * 4;
            #pragma unroll
            for (int p = 0; p < 2; p++) {
                int mm = m + p * 32;
                float4 v = cvt_tf32_4(*(const float4*)(src + (size_t)(t * M_ + ridx[mm]) * K + k0 + kk));
                *(float4*)&As[mm][kk] = v;
            }
        }
        {
            #pragma unroll
            for (int p = 0; p < 4; p++) {
                int idx4 = tid + p * 256;
                int row = idx4 >> 5, c4 = (idx4 & 31) * 4;
                float4 v = cvt_tf32_4(*(const float4*)(W + (size_t)(k0 + row) * DH + c4));
                *(float4*)&Ws[row][c4] = v;
            }
        }
        __syncthreads();
        #pragma unroll
        for (int s = 0; s < 4; s++) {
            int kk = s * 8;
            unsigned a0 = __float_as_uint(As[mq + gID][kk + tig]);
            unsigned a1 = __float_as_uint(As[mq + gID + 8][kk + tig]);
            unsigned a2 = __float_as_uint(As[mq + gID][kk + tig + 4]);
            unsigned a3 = __float_as_uint(As[mq + gID + 8][kk + tig + 4]);
            #pragma unroll
            for (int ns = 0; ns < 8; ns++) {
                int col = nh + ns * 8 + gID;
                unsigned b0 = __float_as_uint(Ws[kk + tig][col]);
                unsigned b1 = __float_as_uint(Ws[kk + tig + 4][col]);
                mma_tf32(o[ns], a0, a1, a2, a3, b0, b1);
            }
        }
    }
    int r0 = mq + gID, r1 = r0 + 8;
    if (mbase + r0 < mc) {
        float s = rn[r0];
        float* dst = g_z + (size_t)(t * M_ + ridx[r0]) * DH + nh;
        #pragma unroll
        for (int ns = 0; ns < 8; ns++) {
            float2 v = {o[ns][0] * s, o[ns][1] * s};
            *(float2*)(dst + ns * 8 + 2 * tig) = v;
        }
    }
    if (mbase + r1 < mc) {
        float s = rn[r1];
        float* dst = g_z + (size_t)(t * M_ + ridx[r1]) * DH + nh;
        #pragma unroll
        for (int ns = 0; ns < 8; ns++) {
            float2 v = {o[ns][2] * s, o[ns][3] * s};
            *(float2*)(dst + ns * 8 + 2 * tig) = v;
        }
    }
}

// QKV GEMM via tf32 mma
__global__ void __launch_bounds__(256) k_gemm_qkv(const float* __restrict__ qw,
                                                  const float* __restrict__ kw,
                                                  const float* __restrict__ vw) {
    int t = blockIdx.x;
    int mc = g_mcnt[t];
    int mbase = blockIdx.y * 64;
    if (mbase >= mc) return;
    int sel = blockIdx.z;
    const float* W  = (sel == 0) ? qw : (sel == 1) ? kw : vw;
    const float* tb = (sel == 0) ? g_qt : (sel == 1) ? g_kt : g_vt;
    float* out      = (sel == 0) ? g_Q : (sel == 1) ? g_K : g_V;

    __shared__ float As[64][36];
    __shared__ float Ws[32][WSTR];
    __shared__ int   ridx[64];
    int tid = threadIdx.x;
    if (tid < 64) {
        int lp = mbase + tid;
        ridx[tid] = g_list[t * M_ + (lp < mc ? lp : mc - 1)];
    }
    int w = tid >> 5, lane = tid & 31;
    int gID = lane >> 2, tig = lane & 3;
    int mq = (w & 3) * 16, nh = (w >> 2) * 64;

    float o[8][4];
    #pragma unroll
    for (int i = 0; i < 8; i++)
        #pragma unroll
        for (int j = 0; j < 4; j++) o[i][j] = 0.0f;

    for (int k0 = 0; k0 < DH; k0 += 32) {
        __syncthreads();
        {
            int m = tid >> 3;
            int kk = (tid & 7) * 4;
            #pragma unroll
            for (int p = 0; p < 2; p++) {
                int mm = m + p * 32;
                float4 v = cvt_tf32_4(*(const float4*)(g_h + (size_t)(t * M_ + ridx[mm]) * DH + k0 + kk));
                *(float4*)&As[mm][kk] = v;
            }
        }
        {
            #pragma unroll
            for (int p = 0; p < 4; p++) {
                int idx4 = tid + p * 256;
                int row = idx4 >> 5, c4 = (idx4 & 31) * 4;
                float4 v = cvt_tf32_4(*(const float4*)(W + (size_t)(k0 + row) * DH + c4));
                *(float4*)&Ws[row][c4] = v;
            }
        }
        __syncthreads();
        #pragma unroll
        for (int s = 0; s < 4; s++) {
            int kk = s * 8;
            unsigned a0 = __float_as_uint(As[mq + gID][kk + tig]);
            unsigned a1 = __float_as_uint(As[mq + gID + 8][kk + tig]);
            unsigned a2 = __float_as_uint(As[mq + gID][kk + tig + 4]);
            unsigned a3 = __float_as_uint(As[mq + gID + 8][kk + tig + 4]);
            #pragma unroll
            for (int ns = 0; ns < 8; ns++) {
                int col = nh + ns * 8 + gID;
                unsigned b0 = __float_as_uint(Ws[kk + tig][col]);
                unsigned b1 = __float_as_uint(Ws[kk + tig + 4][col]);
                mma_tf32(o[ns], a0, a1, a2, a3, b0, b1);
            }
        }
    }
    int r0 = mq + gID, r1 = r0 + 8;
    if (mbase + r0 < mc) {
        float* dst = out + (size_t)(t * M_ + mbase + r0) * DH + nh;
        #pragma unroll
        for (int ns = 0; ns < 8; ns++) {
            int c = ns * 8 + 2 * tig;
            float2 bv = *(const float2*)(tb + t * DH + nh + c);
            float2 v = {o[ns][0] + bv.x, o[ns][1] + bv.y};
            *(float2*)(dst + c) = v;
        }
    }
    if (mbase + r1 < mc) {
        float* dst = out + (size_t)(t * M_ + mbase + r1) * DH + nh;
        #pragma unroll
        for (int ns = 0; ns < 8; ns++) {
            int c = ns * 8 + 2 * tig;
            float2 bv = *(const float2*)(tb + t * DH + nh + c);
            float2 v = {o[ns][2] + bv.x, o[ns][3] + bv.y};
            *(float2*)(dst + c) = v;
        }
    }
}

__global__ void __launch_bounds__(256) k_out2(float* __restrict__ out) {
    int t = blockIdx.x;
    int mc = g_mcnt[t];
    int mbase = blockIdx.y * 64;
    if (mbase >= mc) return;
    __shared__ float As[64][36];
    __shared__ float Ws2[32][DO];
    __shared__ int   ridx[64];
    int tid = threadIdx.x;
    if (tid < 64) {
        int lp = mbase + tid;
        ridx[tid] = g_list[t * M_ + (lp < mc ? lp : mc - 1)];
    }
    float acc[4][2];
    #pragma unroll
    for (int i = 0; i < 4; i++) { acc[i][0] = 0.0f; acc[i][1] = 0.0f; }
    int ty = tid >> 4, tx = tid & 15;
    int m0 = ty * 4, n0 = tx * 2;

    for (int k0 = 0; k0 < DH; k0 += 32) {
        __syncthreads();
        {
            int m = tid >> 3;
            int kk = (tid & 7) * 4;
            #pragma unroll
            for (int p = 0; p < 2; p++) {
                int mm = m + p * 32;
                int lp = mbase + mm;
                int lpc = (lp < mc ? lp : mc - 1);
                float4 v = *(const float4*)(g_agg + (size_t)(t * M_ + lpc) * DH + k0 + kk);
                As[mm][kk] = v.x; As[mm][kk + 1] = v.y; As[mm][kk + 2] = v.z; As[mm][kk + 3] = v.w;
            }
        }
        {
            float4* Ws4 = (float4*)Ws2;
            const float4* W4 = (const float4*)(g_wc + (size_t)k0 * DO);
            Ws4[tid] = W4[tid];
        }
        __syncthreads();
        #pragma unroll
        for (int kk = 0; kk < 32; kk++) {
            float a0 = As[m0][kk], a1 = As[m0 + 1][kk], a2 = As[m0 + 2][kk], a3 = As[m0 + 3][kk];
            float2 b = *(float2*)&Ws2[kk][n0];
            acc[0][0] += a0 * b.x; acc[0][1] += a0 * b.y;
            acc[1][0] += a1 * b.x; acc[1][1] += a1 * b.y;
            acc[2][0] += a2 * b.x; acc[2][1] += a2 * b.y;
            acc[3][0] += a3 * b.x; acc[3][1] += a3 * b.y;
        }
    }
    float2 bc = *(const float2*)(g_bc + n0);
    #pragma unroll
    for (int i = 0; i < 4; i++) {
        int lp = mbase + m0 + i;
        if (lp < mc) {
            int node = ridx[m0 + i];
            float2 o = {acc[i][0] + bc.x, acc[i][1] + bc.y};
            *(float2*)(out + ((size_t)node * T_ + t) * DO + n0) = o;
        }
    }
}

// ---------------- sparse aggregation + bias + ReLU (float4, 4 nodes/block) ----------------
__global__ void __launch_bounds__(128) k_spmm(const float* __restrict__ bias) {
    int t = blockIdx.x;
    int lp = blockIdx.y * 4 + (threadIdx.x >> 5);
    if (lp >= g_mcnt[t]) return;
    int i = g_list[t * M_ + lp];
    int f4 = (threadIdx.x & 31) * 4;
    float4 acc = *(const float4*)(g_z + (size_t)(t * M_ + i) * DH + f4);  // self-loop
    const int* c8 = g_cnt8 + (t * M_ + i) * NJC;
    #pragma unroll
    for (int jc = 0; jc < NJC; jc++) {
        int c = c8[jc];
        const int* cl = g_col + ((size_t)((t * M_ + i) * NJC + jc)) * CAPC;
        for (int e = 0; e < c; e++) {
            int j = cl[e];
            float4 v = *(const float4*)(g_z + (size_t)(t * M_ + j) * DH + f4);
            acc.x += v.x; acc.y += v.y; acc.z += v.z; acc.w += v.w;
        }
    }
    float nv = g_nrm[t * M_ + i];
    float4 b = *(const float4*)(bias + f4);
    float4 r;
    r.x = fmaxf(acc.x * nv + b.x, 0.0f);
    r.y = fmaxf(acc.y * nv + b.y, 0.0f);
    r.z = fmaxf(acc.z * nv + b.z, 0.0f);
    r.w = fmaxf(acc.w * nv + b.w, 0.0f);
    *(float4*)(g_h + (size_t)(t * M_ + i) * DH + f4) = r;
}

// ---------------- flash attention: QT=64, tf32 mma.sync ----------------
#define QT 64
#define KC 64
#define QSTR 132      // ≡4 mod 32 — A-frag loads conflict-free
#define KSTR 132      // ≡4 — QK B-frag conflict-free
#define VSTR 136      // ≡8 — PV B-frag conflict-free
#define SSTR 68       // ≡4
extern __shared__ float smattn[];
__global__ void __launch_bounds__(256) k_attn() {
    int t = blockIdx.x;
    int mc = g_mcnt[t];
    int qb = blockIdx.y * QT;
    if (qb >= mc) return;
    float* Qs   = smattn;                 // QT*QSTR
    float* Ks   = Qs + QT * QSTR;         // KC*VSTR buffer (K: stride KSTR, V: stride VSTR)
    float* S    = Ks + KC * VSTR;         // QT*SSTR
    float* rowm = S + QT * SSTR;          // QT
    float* rowl = rowm + QT;
    float* rowsc= rowl + QT;
    int tid = threadIdx.x;
    int w = tid >> 5, lane = tid & 31;
    int gID = lane >> 2, tig = lane & 3;
    int mq = (w & 3) * 16;
    int dh = w >> 2;
    int nv = min(QT, mc - qb);
    const float scl = 0.08838834764831845f;

    // Q fill (tf32-rounded)
    for (int p = 0; p < 8; p++) {
        int idx4 = tid + p * 256;
        int q = idx4 >> 5, d4 = (idx4 & 31) * 4;
        float4 v = {0.f, 0.f, 0.f, 0.f};
        if (q < nv) v = cvt_tf32_4(*(const float4*)(g_Q + (size_t)(t * M_ + qb + q) * DH + d4));
        *(float4*)(Qs + q * QSTR + d4) = v;
    }
    if (tid < QT) { rowm[tid] = -1e30f; rowl[tid] = 0.0f; }

    float o[8][4];
    #pragma unroll
    for (int i = 0; i < 8; i++)
        #pragma unroll
        for (int j = 0; j < 4; j++) o[i][j] = 0.0f;

    for (int kb = 0; kb < mc; kb += KC) {
        int kn = min(KC, mc - kb);
        __syncthreads();
        // K fill (stride KSTR, tf32)
        for (int p = 0; p < 8; p++) {
            int idx4 = tid + p * 256;
            int k = idx4 >> 5, d4 = (idx4 & 31) * 4;
            float4 v = {0.f, 0.f, 0.f, 0.f};
            if (k < kn) v = cvt_tf32_4(*(const float4*)(g_K + (size_t)(t * M_ + kb + k) * DH + d4));
            *(float4*)(Ks + k * KSTR + d4) = v;
        }
        __syncthreads();
        // QK scores: warp tile 16q x 64k over d-half
        float c[8][4];
        #pragma unroll
        for (int i = 0; i < 8; i++)
            #pragma unroll
            for (int j = 0; j < 4; j++) c[i][j] = 0.0f;
        {
            int dbase = dh * 64;
            #pragma unroll
            for (int s = 0; s < 8; s++) {
                int d0 = dbase + s * 8;
                unsigned a0 = __float_as_uint(Qs[(mq + gID) * QSTR + d0 + tig]);
                unsigned a1 = __float_as_uint(Qs[(mq + gID + 8) * QSTR + d0 + tig]);
                unsigned a2 = __float_as_uint(Qs[(mq + gID) * QSTR + d0 + tig + 4]);
                unsigned a3 = __float_as_uint(Qs[(mq + gID + 8) * QSTR + d0 + tig + 4]);
                #pragma unroll
                for (int ns = 0; ns < 8; ns++) {
                    unsigned b0 = __float_as_uint(Ks[(ns * 8 + gID) * KSTR + d0 + tig]);
                    unsigned b1 = __float_as_uint(Ks[(ns * 8 + gID) * KSTR + d0 + tig + 4]);
                    mma_tf32(c[ns], a0, a1, a2, a3, b0, b1);
                }
            }
        }
        // combine d-halves deterministically
        if (dh == 0) {
            #pragma unroll
            for (int ns = 0; ns < 8; ns++) {
                int col = ns * 8 + 2 * tig;
                S[(mq + gID) * SSTR + col]     = c[ns][0];
                S[(mq + gID) * SSTR + col + 1] = c[ns][1];
                S[(mq + gID + 8) * SSTR + col]     = c[ns][2];
                S[(mq + gID + 8) * SSTR + col + 1] = c[ns][3];
            }
        }
        __syncthreads();
        if (dh == 1) {
            #pragma unroll
            for (int ns = 0; ns < 8; ns++) {
                int col = ns * 8 + 2 * tig;
                int r0 = (mq + gID) * SSTR, r1 = (mq + gID + 8) * SSTR;
                S[r0 + col]     = (col     < kn) ? (S[r0 + col]     + c[ns][0]) * scl : -1e30f;
                S[r0 + col + 1] = (col + 1 < kn) ? (S[r0 + col + 1] + c[ns][1]) * scl : -1e30f;
                S[r1 + col]     = (col     < kn) ? (S[r1 + col]     + c[ns][2]) * scl : -1e30f;
                S[r1 + col + 1] = (col + 1 < kn) ? (S[r1 + col + 1] + c[ns][3]) * scl : -1e30f;
            }
        }
        __syncthreads();
        // online softmax: 8 warps x 8 rows, 4 lanes per row; P stored tf32-rounded
        {
            int row = w * 8 + (lane >> 2);
            int l4 = lane & 3;
            float* Sr = S + row * SSTR;
            float mloc = -1e30f;
            for (int k = l4; k < KC; k += 4) mloc = fmaxf(mloc, Sr[k]);
            #pragma unroll
            for (int off = 2; off >= 1; off >>= 1)
                mloc = fmaxf(mloc, __shfl_xor_sync(0xffffffffu, mloc, off));
            float oldm = rowm[row];
            float newm = fmaxf(oldm, mloc);
            float ssum = 0.0f;
            for (int k = l4; k < KC; k += 4) {
                float p = cvt_tf32(__expf(Sr[k] - newm));
                Sr[k] = p;
                ssum += p;
            }
            #pragma unroll
            for (int off = 2; off >= 1; off >>= 1)
                ssum += __shfl_xor_sync(0xffffffffu, ssum, off);
            if (l4 == 0) {
                float sc = __expf(oldm - newm);
                rowsc[row] = sc;
                rowl[row] = rowl[row] * sc + ssum;
                rowm[row] = newm;
            }
        }
        __syncthreads();
        // rescale PV accumulators
        {
            float sc0 = rowsc[mq + gID];
            float sc1 = rowsc[mq + gID + 8];
            #pragma unroll
            for (int ns = 0; ns < 8; ns++) {
                o[ns][0] *= sc0; o[ns][1] *= sc0;
                o[ns][2] *= sc1; o[ns][3] *= sc1;
            }
        }
        // V fill (stride VSTR, tf32)
        for (int p = 0; p < 8; p++) {
            int idx4 = tid + p * 256;
            int k = idx4 >> 5, d4 = (idx4 & 31) * 4;
            float4 v = {0.f, 0.f, 0.f, 0.f};
            if (k < kn) v = cvt_tf32_4(*(const float4*)(g_V + (size_t)(t * M_ + kb + k) * DH + d4));
            *(float4*)(Ks + k * VSTR + d4) = v;
        }
        __syncthreads();
        // PV: warp tile 16q x 64d (d-half dh)
        {
            int dbase = dh * 64;
            #pragma unroll
            for (int s = 0; s < 8; s++) {
                int k0 = s * 8;
                unsigned a0 = __float_as_uint(S[(mq + gID) * SSTR + k0 + tig]);
                unsigned a1 = __float_as_uint(S[(mq + gID + 8) * SSTR + k0 + tig]);
                unsigned a2 = __float_as_uint(S[(mq + gID) * SSTR + k0 + tig + 4]);
                unsigned a3 = __float_as_uint(S[(mq + gID + 8) * SSTR + k0 + tig + 4]);
                #pragma unroll
                for (int ns = 0; ns < 8; ns++) {
                    int col = dbase + ns * 8 + gID;
                    unsigned b0 = __float_as_uint(Ks[(k0 + tig) * VSTR + col]);
                    unsigned b1 = __float_as_uint(Ks[(k0 + tig + 4) * VSTR + col]);
                    mma_tf32(o[ns], a0, a1, a2, a3, b0, b1);
                }
            }
        }
    }
    __syncthreads();
    // final normalize + store
    {
        int dbase = dh * 64;
        int r0 = mq + gID, r1 = mq + gID + 8;
        if (r0 < nv) {
            float inv = 1.0f / rowl[r0];
            float* dst = g_agg + (size_t)(t * M_ + qb + r0) * DH + dbase;
            #pragma unroll
            for (int ns = 0; ns < 8; ns++) {
                float2 v = {o[ns][0] * inv, o[ns][1] * inv};
                *(float2*)(dst + ns * 8 + 2 * tig) = v;
            }
        }
        if (r1 < nv) {
            float inv = 1.0f / rowl[r1];
            float* dst = g_agg + (size_t)(t * M_ + qb + r1) * DH + dbase;
            #pragma unroll
            for (int ns = 0; ns < 8; ns++) {
                float2 v = {o[ns][2] * inv, o[ns][3] * inv};
                *(float2*)(dst + ns * 8 + 2 * tig) = v;
            }
        }
    }
}

// ---------------- launch ----------------
extern "C" void kernel_launch(void* const* d_in, const int* in_sizes, int n_in,
                              void* d_out, int out_size) {
    const float* x   = (const float*)d_in[0];
    const float* A   = (const float*)d_in[1];
    const void*  em  = d_in[2];
    const float* w1  = (const float*)d_in[3];
    const float* b1  = (const float*)d_in[4];
    const float* w2  = (const float*)d_in[5];
    const float* b2  = (const float*)d_in[6];
    const float* tw  = (const float*)d_in[7];
    const float* tb  = (const float*)d_in[8];
    const float* qw  = (const float*)d_in[9];
    const float* qb  = (const float*)d_in[10];
    const float* kw  = (const float*)d_in[11];
    const float* kb  = (const float*)d_in[12];
    const float* vw  = (const float*)d_in[13];
    const float* vb  = (const float*)d_in[14];
    const float* ow  = (const float*)d_in[15];
    const float* ob  = (const float*)d_in[16];
    const float* fcw = (const float*)d_in[17];
    const float* fcb = (const float*)d_in[18];

    const int ATTN_SMEM = (QT * QSTR + KC * VSTR + QT * SSTR + 3 * QT) * 4; // 86784 B
    cudaFuncSetAttribute(k_attn, cudaFuncAttributeMaxDynamicSharedMemorySize, ATTN_SMEM);

    k_detect<<<1, 256>>>(em);
    k_mask<<<(T_ * M_) / 256, 256>>>(em);
    k_compact<<<T_, 1024>>>();
    k_edges<<<dim3(T_, NJC, M_ / 256), 256>>>(A);
    k_nrm<<<(T_ * M_) / 256, 256>>>();
    k_tbias<<<T_, DH>>>(tw, tb, qw, qb, kw, kb, vw, vb);
    k_comb<<<16, 256>>>(ow, ob, fcw, fcb);
    k_gemm_z<<<dim3(T_, M_ / 64), 256>>>(x, w1, 0);
    k_spmm<<<dim3(T_, M_ / 4), 128>>>(b1);
    k_gemm_z<<<dim3(T_, M_ / 64), 256>>>(nullptr, w2, 1);
    k_spmm<<<dim3(T_, M_ / 4), 128>>>(b2);
    k_gemm_qkv<<<dim3(T_, M_ / 64, 3), 256>>>(qw, kw, vw);
    k_attn<<<dim3(T_, M_ / QT), 256, ATTN_SMEM>>>();
    cudaMemsetAsync(d_out, 0, (size_t)out_size * sizeof(float));
    k_out2<<<dim3(T_, M_ / 64), 256>>>((float*)d_out);
}

// round 15
// speedup vs baseline: 1.5407x; 1.0076x over previous
#include <cuda_runtime.h>
#include <cuda_bf16.h>
#include <math.h>

#define T_  12
#define M_  2048
#define B_  2
#define N_  1024
#define DIN 64
#define DH  128
#define DT  16
#define DO  32
#define NJC 8
#define CAPC 32

// mma.tf32 — operands passed as raw fp32 bits (HW truncates mantissa to tf32)
__device__ __forceinline__ void mma_tf32(float* c,
                                         unsigned a0, unsigned a1, unsigned a2, unsigned a3,
                                         unsigned b0, unsigned b1) {
    asm("mma.sync.aligned.m16n8k8.row.col.f32.tf32.tf32.f32 "
        "{%0,%1,%2,%3}, {%4,%5,%6,%7}, {%8,%9}, {%0,%1,%2,%3};"
        : "+f"(c[0]), "+f"(c[1]), "+f"(c[2]), "+f"(c[3])
        : "r"(a0), "r"(a1), "r"(a2), "r"(a3), "r"(b0), "r"(b1));
}

// ---------------- device scratch ---------------
__device__ int   g_mdtype;
__device__ int   g_mask[T_ * M_];
__device__ int   g_list[T_ * M_];
__device__ int   g_mcnt[T_];
__device__ int   g_cnt8[T_ * M_ * NJC];
__device__ int   g_col [T_ * M_ * NJC * CAPC];
__device__ float g_nrm [T_ * M_];
__device__ float g_z   [T_ * M_ * DH];
__device__ float g_h   [T_ * M_ * DH];
__device__ float g_Q   [T_ * M_ * DH];
__device__ float g_K   [T_ * M_ * DH];
__device__ float g_V   [T_ * M_ * DH];
__device__ float g_agg [T_ * M_ * DH];
__device__ float g_qt  [T_ * DH];
__device__ float g_kt  [T_ * DH];
__device__ float g_vt  [T_ * DH];
__device__ float g_wc  [DH * DO];
__device__ float g_bc  [DO];

extern __shared__ float smdyn[];

// ---------------- mask dtype detection ----------------
__global__ void k_detect(const void* p) {
    const int*   wi = (const int*)p;
    const float* wf = (const float*)p;
    int oki = 1, okf = 1;
    for (int r = 0; r < 8; r++) {
        int idx = r * 256 + threadIdx.x;
        int w  = wi[idx];
        float f = wf[idx];
        oki &= (w == 0 || w == 1);
        okf &= (f == 0.0f || f == 1.0f);
    }
    oki = __syncthreads_and(oki);
    okf = __syncthreads_and(okf);
    if (threadIdx.x == 0) g_mdtype = okf ? 2 : (oki ? 1 : 0);
}

__global__ void k_mask(const void* em) {
    int idx = blockIdx.x * 256 + threadIdx.x;
    int t = idx >> 11, m = idx & (M_ - 1);
    int b = m >> 10, n = m & (N_ - 1);
    int src = (b * T_ + t) * N_ + n;
    int dt = g_mdtype;
    int v;
    if (dt == 1)      v = ((const int*)em)[src] != 0;
    else if (dt == 2) v = ((const float*)em)[src] != 0.0f;
    else              v = ((const unsigned char*)em)[src] != 0;
    g_mask[idx] = v;
}

__global__ void __launch_bounds__(1024) k_compact() {
    int t = blockIdx.x, tid = threadIdx.x;
    __shared__ int wsum[32];
    __shared__ int sbase;
    if (tid == 0) sbase = 0;
    __syncthreads();
    for (int half = 0; half < 2; half++) {
        int i = half * 1024 + tid;
        int mv = g_mask[t * M_ + i];
        unsigned b = __ballot_sync(0xffffffffu, mv);
        int lane = tid & 31, wid = tid >> 5;
        if (lane == 0) wsum[wid] = __popc(b);
        __syncthreads();
        int woff = 0;
        for (int w = 0; w < wid; w++) woff += wsum[w];
        if (mv) g_list[t * M_ + sbase + woff + __popc(b & ((1u << lane) - 1u))] = i;
        __syncthreads();
        if (tid == 0) {
            int tot = 0;
            for (int w = 0; w < 32; w++) tot += wsum[w];
            sbase += tot;
        }
        __syncthreads();
    }
    if (tid == 0) g_mcnt[t] = sbase;
}

// streaming A scan (unconditional loads keep MLP high)
__global__ void k_edges(const float* __restrict__ A) {
    int t = blockIdx.x, jc = blockIdx.y, ic = blockIdx.z;
    int i = ic * 256 + threadIdx.x;
    __shared__ int mj[256];
    int jbase = jc * 256;
    mj[threadIdx.x] = g_mask[t * M_ + jbase + threadIdx.x];
    __syncthreads();
    int mi = g_mask[t * M_ + i];
    int cnt = 0;
    int* cols = g_col + ((size_t)((t * M_ + i) * NJC + jc)) * CAPC;
    if (mi) {
        const float* Ab = A + (size_t)(t * M_ + jbase) * M_ + i;
        #pragma unroll 8
        for (int jj = 0; jj < 256; jj++) {
            float a = Ab[(size_t)jj * M_];
            if (a != 0.0f && mj[jj] && cnt < CAPC) cols[cnt++] = jbase + jj;
        }
    }
    g_cnt8[(t * M_ + i) * NJC + jc] = cnt;
}

__global__ void k_nrm() {
    int idx = blockIdx.x * 256 + threadIdx.x;
    float nv = 0.0f;
    if (g_mask[idx]) {
        int c = 1;
        #pragma unroll
        for (int jc = 0; jc < NJC; jc++) c += g_cnt8[idx * NJC + jc];
        nv = rsqrtf((float)c);
    }
    g_nrm[idx] = nv;
}

__global__ void k_tbias(const float* __restrict__ tw, const float* __restrict__ tb,
                        const float* __restrict__ qw, const float* __restrict__ qb,
                        const float* __restrict__ kw, const float* __restrict__ kb,
                        const float* __restrict__ vw, const float* __restrict__ vb) {
    int t = blockIdx.x, f = threadIdx.x;
    float tv[DT];
    #pragma unroll
    for (int d = 0; d < DT; d++) tv[d] = sinf((float)t * tw[d] + tb[d]);
    float aq = qb[f], ak = kb[f], av = vb[f];
    #pragma unroll
    for (int d = 0; d < DT; d++) {
        aq += tv[d] * qw[(DH + d) * DH + f];
        ak += tv[d] * kw[(DH + d) * DH + f];
        av += tv[d] * vw[(DH + d) * DH + f];
    }
    g_qt[t * DH + f] = aq;
    g_kt[t * DH + f] = ak;
    g_vt[t * DH + f] = av;
}

__global__ void k_comb(const float* __restrict__ ow, const float* __restrict__ ob,
                       const float* __restrict__ fcw, const float* __restrict__ fcb) {
    int idx = blockIdx.x * 256 + threadIdx.x;
    int d = idx >> 5, f = idx & 31;
    float acc = 0.0f;
    #pragma unroll 8
    for (int e = 0; e < DH; e++) acc += ow[d * DH + e] * fcw[e * DO + f];
    g_wc[idx] = acc;
    if (idx < DO) {
        float b = fcb[idx];
        #pragma unroll 8
        for (int e = 0; e < DH; e++) b += ob[e] * fcw[e * DO + idx];
        g_bc[idx] = b;
    }
}

// ============ tf32 mma GEMM: 64 nodes x 128 features ============
#define WSTR 136
__global__ void __launch_bounds__(256) k_gemm_z(const float* __restrict__ xsrc,
                                                const float* __restrict__ W, int mode) {
    int t = blockIdx.x;
    int mc = g_mcnt[t];
    int mbase = blockIdx.y * 64;
    if (mbase >= mc) return;
    const float* src = (mode == 0) ? xsrc : (const float*)g_h;
    const int K = (mode == 0) ? DIN : DH;

    __shared__ float As[64][36];
    __shared__ float Ws[32][WSTR];
    __shared__ int   ridx[64];
    __shared__ float rn[64];
    int tid = threadIdx.x;
    if (tid < 64) {
        int lp = mbase + tid;
        int i = g_list[t * M_ + (lp < mc ? lp : mc - 1)];
        ridx[tid] = i;
        rn[tid] = g_nrm[t * M_ + i];
    }
    int w = tid >> 5, lane = tid & 31;
    int gID = lane >> 2, tig = lane & 3;
    int mq = (w & 3) * 16, nh = (w >> 2) * 64;

    float o[8][4];
    #pragma unroll
    for (int i = 0; i < 8; i++)
        #pragma unroll
        for (int j = 0; j < 4; j++) o[i][j] = 0.0f;

    for (int k0 = 0; k0 < K; k0 += 32) {
        __syncthreads();
        {
            int m = tid >> 3;
            int kk = (tid & 7) * 4;
            #pragma unroll
            for (int p = 0; p < 2; p++) {
                int mm = m + p * 32;
                float4 v = *(const float4*)(src + (size_t)(t * M_ + ridx[mm]) * K + k0 + kk);
                *(float4*)&As[mm][kk] = v;
            }
        }
        {
            #pragma unroll
            for (int p = 0; p < 4; p++) {
                int idx4 = tid + p * 256;
                int row = idx4 >> 5, c4 = (idx4 & 31) * 4;
                float4 v = *(const float4*)(W + (size_t)(k0 + row) * DH + c4);
                *(float4*)&Ws[row][c4] = v;
            }
        }
        __syncthreads();
        #pragma unroll
        for (int s = 0; s < 4; s++) {
            int kk = s * 8;
            unsigned a0 = __float_as_uint(As[mq + gID][kk + tig]);
            unsigned a1 = __float_as_uint(As[mq + gID + 8][kk + tig]);
            unsigned a2 = __float_as_uint(As[mq + gID][kk + tig + 4]);
            unsigned a3 = __float_as_uint(As[mq + gID + 8][kk + tig + 4]);
            #pragma unroll
            for (int ns = 0; ns < 8; ns++) {
                int col = nh + ns * 8 + gID;
                unsigned b0 = __float_as_uint(Ws[kk + tig][col]);
                unsigned b1 = __float_as_uint(Ws[kk + tig + 4][col]);
                mma_tf32(o[ns], a0, a1, a2, a3, b0, b1);
            }
        }
    }
    int r0 = mq + gID, r1 = r0 + 8;
    if (mbase + r0 < mc) {
        float s = rn[r0];
        float* dst = g_z + (size_t)(t * M_ + ridx[r0]) * DH + nh;
        #pragma unroll
        for (int ns = 0; ns < 8; ns++) {
            float2 v = {o[ns][0] * s, o[ns][1] * s};
            *(float2*)(dst + ns * 8 + 2 * tig) = v;
        }
    }
    if (mbase + r1 < mc) {
        float s = rn[r1];
        float* dst = g_z + (size_t)(t * M_ + ridx[r1]) * DH + nh;
        #pragma unroll
        for (int ns = 0; ns < 8; ns++) {
            float2 v = {o[ns][2] * s, o[ns][3] * s};
            *(float2*)(dst + ns * 8 + 2 * tig) = v;
        }
    }
}

// Fused QKV GEMM: A tile (64 x 128) resident in dynamic smem; loop over 3 weights.
#define ASTR 132
__global__ void __launch_bounds__(256) k_gemm_qkv(const float* __restrict__ qw,
                                                  const float* __restrict__ kw,
                                                  const float* __restrict__ vw) {
    int t = blockIdx.x;
    int mc = g_mcnt[t];
    int mbase = blockIdx.y * 64;
    if (mbase >= mc) return;
    float* As = smdyn;                    // 64*ASTR
    float* Ws = As + 64 * ASTR;           // 32*WSTR
    int*  ridx = (int*)(Ws + 32 * WSTR);  // 64
    int tid = threadIdx.x;
    if (tid < 64) {
        int lp = mbase + tid;
        ridx[tid] = g_list[t * M_ + (lp < mc ? lp : mc - 1)];
    }
    __syncthreads();
    // full A tile once
    for (int p = 0; p < 8; p++) {
        int idx4 = tid + p * 256;
        int q = idx4 >> 5, d4 = (idx4 & 31) * 4;
        float4 v = *(const float4*)(g_h + (size_t)(t * M_ + ridx[q]) * DH + d4);
        *(float4*)(As + q * ASTR + d4) = v;
    }
    int w = tid >> 5, lane = tid & 31;
    int gID = lane >> 2, tig = lane & 3;
    int mq = (w & 3) * 16, nh = (w >> 2) * 64;
    int r0 = mq + gID, r1 = r0 + 8;

    for (int sel = 0; sel < 3; sel++) {
        const float* W  = (sel == 0) ? qw : (sel == 1) ? kw : vw;
        const float* tb = (sel == 0) ? g_qt : (sel == 1) ? g_kt : g_vt;
        float* out      = (sel == 0) ? g_Q : (sel == 1) ? g_K : g_V;

        float o[8][4];
        #pragma unroll
        for (int i = 0; i < 8; i++)
            #pragma unroll
            for (int j = 0; j < 4; j++) o[i][j] = 0.0f;

        for (int k0 = 0; k0 < DH; k0 += 32) {
            __syncthreads();
            #pragma unroll
            for (int p = 0; p < 4; p++) {
                int idx4 = tid + p * 256;
                int row = idx4 >> 5, c4 = (idx4 & 31) * 4;
                float4 v = *(const float4*)(W + (size_t)(k0 + row) * DH + c4);
                *(float4*)&Ws[row * WSTR + c4] = v;
            }
            __syncthreads();
            #pragma unroll
            for (int s = 0; s < 4; s++) {
                int kk = k0 + s * 8;
                unsigned a0 = __float_as_uint(As[(mq + gID) * ASTR + kk + tig]);
                unsigned a1 = __float_as_uint(As[(mq + gID + 8) * ASTR + kk + tig]);
                unsigned a2 = __float_as_uint(As[(mq + gID) * ASTR + kk + tig + 4]);
                unsigned a3 = __float_as_uint(As[(mq + gID + 8) * ASTR + kk + tig + 4]);
                #pragma unroll
                for (int ns = 0; ns < 8; ns++) {
                    int col = nh + ns * 8 + gID;
                    unsigned b0 = __float_as_uint(Ws[(s * 8 + tig) * WSTR + col]);
                    unsigned b1 = __float_as_uint(Ws[(s * 8 + tig + 4) * WSTR + col]);
                    mma_tf32(o[ns], a0, a1, a2, a3, b0, b1);
                }
            }
        }
        if (mbase + r0 < mc) {
            float* dst = out + (size_t)(t * M_ + mbase + r0) * DH + nh;
            #pragma unroll
            for (int ns = 0; ns < 8; ns++) {
                int c = ns * 8 + 2 * tig;
                float2 bv = *(const float2*)(tb + t * DH + nh + c);
                float2 v = {o[ns][0] + bv.x, o[ns][1] + bv.y};
                *(float2*)(dst + c) = v;
            }
        }
        if (mbase + r1 < mc) {
            float* dst = out + (size_t)(t * M_ + mbase + r1) * DH + nh;
            #pragma unroll
            for (int ns = 0; ns < 8; ns++) {
                int c = ns * 8 + 2 * tig;
                float2 bv = *(const float2*)(tb + t * DH + nh + c);
                float2 v = {o[ns][2] + bv.x, o[ns][3] + bv.y};
                *(float2*)(dst + c) = v;
            }
        }
    }
}

__global__ void __launch_bounds__(256) k_out2(float* __restrict__ out) {
    int t = blockIdx.x;
    int mc = g_mcnt[t];
    int mbase = blockIdx.y * 64;
    if (mbase >= mc) return;
    __shared__ float As[64][36];
    __shared__ float Ws2[32][DO];
    __shared__ int   ridx[64];
    int tid = threadIdx.x;
    if (tid < 64) {
        int lp = mbase + tid;
        ridx[tid] = g_list[t * M_ + (lp < mc ? lp : mc - 1)];
    }
    float acc[4][2];
    #pragma unroll
    for (int i = 0; i < 4; i++) { acc[i][0] = 0.0f; acc[i][1] = 0.0f; }
    int ty = tid >> 4, tx = tid & 15;
    int m0 = ty * 4, n0 = tx * 2;

    for (int k0 = 0; k0 < DH; k0 += 32) {
        __syncthreads();
        {
            int m = tid >> 3;
            int kk = (tid & 7) * 4;
            #pragma unroll
            for (int p = 0; p < 2; p++) {
                int mm = m + p * 32;
                int lp = mbase + mm;
                int lpc = (lp < mc ? lp : mc - 1);
                float4 v = *(const float4*)(g_agg + (size_t)(t * M_ + lpc) * DH + k0 + kk);
                As[mm][kk] = v.x; As[mm][kk + 1] = v.y; As[mm][kk + 2] = v.z; As[mm][kk + 3] = v.w;
            }
        }
        {
            float4* Ws4 = (float4*)Ws2;
            const float4* W4 = (const float4*)(g_wc + (size_t)k0 * DO);
            Ws4[tid] = W4[tid];
        }
        __syncthreads();
        #pragma unroll
        for (int kk = 0; kk < 32; kk++) {
            float a0 = As[m0][kk], a1 = As[m0 + 1][kk], a2 = As[m0 + 2][kk], a3 = As[m0 + 3][kk];
            float2 b = *(float2*)&Ws2[kk][n0];
            acc[0][0] += a0 * b.x; acc[0][1] += a0 * b.y;
            acc[1][0] += a1 * b.x; acc[1][1] += a1 * b.y;
            acc[2][0] += a2 * b.x; acc[2][1] += a2 * b.y;
            acc[3][0] += a3 * b.x; acc[3][1] += a3 * b.y;
        }
    }
    float2 bc = *(const float2*)(g_bc + n0);
    #pragma unroll
    for (int i = 0; i < 4; i++) {
        int lp = mbase + m0 + i;
        if (lp < mc) {
            int node = ridx[m0 + i];
            float2 o = {acc[i][0] + bc.x, acc[i][1] + bc.y};
            *(float2*)(out + ((size_t)node * T_ + t) * DO + n0) = o;
        }
    }
}

// ---------------- sparse aggregation + bias + ReLU (float4, 4 nodes/block) ----------------
__global__ void __launch_bounds__(128) k_spmm(const float* __restrict__ bias) {
    int t = blockIdx.x;
    int lp = blockIdx.y * 4 + (threadIdx.x >> 5);
    if (lp >= g_mcnt[t]) return;
    int i = g_list[t * M_ + lp];
    int f4 = (threadIdx.x & 31) * 4;
    float4 acc = *(const float4*)(g_z + (size_t)(t * M_ + i) * DH + f4);
    const int* c8 = g_cnt8 + (t * M_ + i) * NJC;
    #pragma unroll
    for (int jc = 0; jc < NJC; jc++) {
        int c = c8[jc];
        const int* cl = g_col + ((size_t)((t * M_ + i) * NJC + jc)) * CAPC;
        for (int e = 0; e < c; e++) {
            int j = cl[e];
            float4 v = *(const float4*)(g_z + (size_t)(t * M_ + j) * DH + f4);
            acc.x += v.x; acc.y += v.y; acc.z += v.z; acc.w += v.w;
        }
    }
    float nv = g_nrm[t * M_ + i];
    float4 b = *(const float4*)(bias + f4);
    float4 r;
    r.x = fmaxf(acc.x * nv + b.x, 0.0f);
    r.y = fmaxf(acc.y * nv + b.y, 0.0f);
    r.z = fmaxf(acc.z * nv + b.z, 0.0f);
    r.w = fmaxf(acc.w * nv + b.w, 0.0f);
    *(float4*)(g_h + (size_t)(t * M_ + i) * DH + f4) = r;
}

// ---------------- flash attention: QT=64, tf32 mma.sync (raw fp32 operands) ----------------
#define QT 64
#define KC 64
#define QSTR 132
#define KSTR 132
#define VSTR 136
#define SSTR 68
__global__ void __launch_bounds__(256) k_attn() {
    int t = blockIdx.x;
    int mc = g_mcnt[t];
    int qb = blockIdx.y * QT;
    if (qb >= mc) return;
    float* Qs   = smdyn;                  // QT*QSTR
    float* Ks   = Qs + QT * QSTR;         // KC*VSTR buffer (K: KSTR, V: VSTR)
    float* S    = Ks + KC * VSTR;         // QT*SSTR
    float* rowm = S + QT * SSTR;
    float* rowl = rowm + QT;
    float* rowsc= rowl + QT;
    int tid = threadIdx.x;
    int w = tid >> 5, lane = tid & 31;
    int gID = lane >> 2, tig = lane & 3;
    int mq = (w & 3) * 16;
    int dh = w >> 2;
    int nv = min(QT, mc - qb);
    const float scl = 0.08838834764831845f;

    for (int p = 0; p < 8; p++) {
        int idx4 = tid + p * 256;
        int q = idx4 >> 5, d4 = (idx4 & 31) * 4;
        float4 v = {0.f, 0.f, 0.f, 0.f};
        if (q < nv) v = *(const float4*)(g_Q + (size_t)(t * M_ + qb + q) * DH + d4);
        *(float4*)(Qs + q * QSTR + d4) = v;
    }
    if (tid < QT) { rowm[tid] = -1e30f; rowl[tid] = 0.0f; }

    float o[8][4];
    #pragma unroll
    for (int i = 0; i < 8; i++)
        #pragma unroll
        for (int j = 0; j < 4; j++) o[i][j] = 0.0f;

    for (int kb = 0; kb < mc; kb += KC) {
        int kn = min(KC, mc - kb);
        __syncthreads();
        for (int p = 0; p < 8; p++) {
            int idx4 = tid + p * 256;
            int k = idx4 >> 5, d4 = (idx4 & 31) * 4;
            float4 v = {0.f, 0.f, 0.f, 0.f};
            if (k < kn) v = *(const float4*)(g_K + (size_t)(t * M_ + kb + k) * DH + d4);
            *(float4*)(Ks + k * KSTR + d4) = v;
        }
        __syncthreads();
        float c[8][4];
        #pragma unroll
        for (int i = 0; i < 8; i++)
            #pragma unroll
            for (int j = 0; j < 4; j++) c[i][j] = 0.0f;
        {
            int dbase = dh * 64;
            #pragma unroll
            for (int s = 0; s < 8; s++) {
                int d0 = dbase + s * 8;
                unsigned a0 = __float_as_uint(Qs[(mq + gID) * QSTR + d0 + tig]);
                unsigned a1 = __float_as_uint(Qs[(mq + gID + 8) * QSTR + d0 + tig]);
                unsigned a2 = __float_as_uint(Qs[(mq + gID) * QSTR + d0 + tig + 4]);
                unsigned a3 = __float_as_uint(Qs[(mq + gID + 8) * QSTR + d0 + tig + 4]);
                #pragma unroll
                for (int ns = 0; ns < 8; ns++) {
                    unsigned b0 = __float_as_uint(Ks[(ns * 8 + gID) * KSTR + d0 + tig]);
                    unsigned b1 = __float_as_uint(Ks[(ns * 8 + gID) * KSTR + d0 + tig + 4]);
                    mma_tf32(c[ns], a0, a1, a2, a3, b0, b1);
                }
            }
        }
        if (dh == 0) {
            #pragma unroll
            for (int ns = 0; ns < 8; ns++) {
                int col = ns * 8 + 2 * tig;
                S[(mq + gID) * SSTR + col]     = c[ns][0];
                S[(mq + gID) * SSTR + col + 1] = c[ns][1];
                S[(mq + gID + 8) * SSTR + col]     = c[ns][2];
                S[(mq + gID + 8) * SSTR + col + 1] = c[ns][3];
            }
        }
        __syncthreads();
        if (dh == 1) {
            #pragma unroll
            for (int ns = 0; ns < 8; ns++) {
                int col = ns * 8 + 2 * tig;
                int r0 = (mq + gID) * SSTR, r1 = (mq + gID + 8) * SSTR;
                S[r0 + col]     = (col     < kn) ? (S[r0 + col]     + c[ns][0]) * scl : -1e30f;
                S[r0 + col + 1] = (col + 1 < kn) ? (S[r0 + col + 1] + c[ns][1]) * scl : -1e30f;
                S[r1 + col]     = (col     < kn) ? (S[r1 + col]     + c[ns][2]) * scl : -1e30f;
                S[r1 + col + 1] = (col + 1 < kn) ? (S[r1 + col + 1] + c[ns][3]) * scl : -1e30f;
            }
        }
        __syncthreads();
        {
            int row = w * 8 + (lane >> 2);
            int l4 = lane & 3;
            float* Sr = S + row * SSTR;
            float mloc = -1e30f;
            for (int k = l4; k < KC; k += 4) mloc = fmaxf(mloc, Sr[k]);
            #pragma unroll
            for (int off = 2; off >= 1; off >>= 1)
                mloc = fmaxf(mloc, __shfl_xor_sync(0xffffffffu, mloc, off));
            float oldm = rowm[row];
            float newm = fmaxf(oldm, mloc);
            float ssum = 0.0f;
            for (int k = l4; k < KC; k += 4) {
                float p = __expf(Sr[k] - newm);
                Sr[k] = p;
                ssum += p;
            }
            #pragma unroll
            for (int off = 2; off >= 1; off >>= 1)
                ssum += __shfl_xor_sync(0xffffffffu, ssum, off);
            if (l4 == 0) {
                float sc = __expf(oldm - newm);
                rowsc[row] = sc;
                rowl[row] = rowl[row] * sc + ssum;
                rowm[row] = newm;
            }
        }
        __syncthreads();
        {
            float sc0 = rowsc[mq + gID];
            float sc1 = rowsc[mq + gID + 8];
            #pragma unroll
            for (int ns = 0; ns < 8; ns++) {
                o[ns][0] *= sc0; o[ns][1] *= sc0;
                o[ns][2] *= sc1; o[ns][3] *= sc1;
            }
        }
        for (int p = 0; p < 8; p++) {
            int idx4 = tid + p * 256;
            int k = idx4 >> 5, d4 = (idx4 & 31) * 4;
            float4 v = {0.f, 0.f, 0.f, 0.f};
            if (k < kn) v = *(const float4*)(g_V + (size_t)(t * M_ + kb + k) * DH + d4);
            *(float4*)(Ks + k * VSTR + d4) = v;
        }
        __syncthreads();
        {
            int dbase = dh * 64;
            #pragma unroll
            for (int s = 0; s < 8; s++) {
                int k0 = s * 8;
                unsigned a0 = __float_as_uint(S[(mq + gID) * SSTR + k0 + tig]);
                unsigned a1 = __float_as_uint(S[(mq + gID + 8) * SSTR + k0 + tig]);
                unsigned a2 = __float_as_uint(S[(mq + gID) * SSTR + k0 + tig + 4]);
                unsigned a3 = __float_as_uint(S[(mq + gID + 8) * SSTR + k0 + tig + 4]);
                #pragma unroll
                for (int ns = 0; ns < 8; ns++) {
                    int col = dbase + ns * 8 + gID;
                    unsigned b0 = __float_as_uint(Ks[(k0 + tig) * VSTR + col]);
                    unsigned b1 = __float_as_uint(Ks[(k0 + tig + 4) * VSTR + col]);
                    mma_tf32(o[ns], a0, a1, a2, a3, b0, b1);
                }
            }
        }
    }
    __syncthreads();
    {
        int dbase = dh * 64;
        int r0 = mq + gID, r1 = mq + gID + 8;
        if (r0 < nv) {
            float inv = 1.0f / rowl[r0];
            float* dst = g_agg + (size_t)(t * M_ + qb + r0) * DH + dbase;
            #pragma unroll
            for (int ns = 0; ns < 8; ns++) {
                float2 v = {o[ns][0] * inv, o[ns][1] * inv};
                *(float2*)(dst + ns * 8 + 2 * tig) = v;
            }
        }
        if (r1 < nv) {
            float inv = 1.0f / rowl[r1];
            float* dst = g_agg + (size_t)(t * M_ + qb + r1) * DH + dbase;
            #pragma unroll
            for (int ns = 0; ns < 8; ns++) {
                float2 v = {o[ns][2] * inv, o[ns][3] * inv};
                *(float2*)(dst + ns * 8 + 2 * tig) = v;
            }
        }
    }
}

// ---------------- launch ----------------
extern "C" void kernel_launch(void* const* d_in, const int* in_sizes, int n_in,
                              void* d_out, int out_size) {
    const float* x   = (const float*)d_in[0];
    const float* A   = (const float*)d_in[1];
    const void*  em  = d_in[2];
    const float* w1  = (const float*)d_in[3];
    const float* b1  = (const float*)d_in[4];
    const float* w2  = (const float*)d_in[5];
    const float* b2  = (const float*)d_in[6];
    const float* tw  = (const float*)d_in[7];
    const float* tb  = (const float*)d_in[8];
    const float* qw  = (const float*)d_in[9];
    const float* qb  = (const float*)d_in[10];
    const float* kw  = (const float*)d_in[11];
    const float* kb  = (const float*)d_in[12];
    const float* vw  = (const float*)d_in[13];
    const float* vb  = (const float*)d_in[14];
    const float* ow  = (const float*)d_in[15];
    const float* ob  = (const float*)d_in[16];
    const float* fcw = (const float*)d_in[17];
    const float* fcb = (const float*)d_in[18];

    const int ATTN_SMEM = (QT * QSTR + KC * VSTR + QT * SSTR + 3 * QT) * 4; // 86784 B
    const int QKV_SMEM  = (64 * ASTR + 32 * WSTR) * 4 + 64 * 4;             // 51456 B
    cudaFuncSetAttribute(k_attn, cudaFuncAttributeMaxDynamicSharedMemorySize, ATTN_SMEM);
    cudaFuncSetAttribute(k_gemm_qkv, cudaFuncAttributeMaxDynamicSharedMemorySize, QKV_SMEM);

    k_detect<<<1, 256>>>(em);
    k_mask<<<(T_ * M_) / 256, 256>>>(em);
    k_compact<<<T_, 1024>>>();
    k_edges<<<dim3(T_, NJC, M_ / 256), 256>>>(A);
    k_nrm<<<(T_ * M_) / 256, 256>>>();
    k_tbias<<<T_, DH>>>(tw, tb, qw, qb, kw, kb, vw, vb);
    k_comb<<<16, 256>>>(ow, ob, fcw, fcb);
    k_gemm_z<<<dim3(T_, M_ / 64), 256>>>(x, w1, 0);
    k_spmm<<<dim3(T_, M_ / 4), 128>>>(b1);
    k_gemm_z<<<dim3(T_, M_ / 64), 256>>>(nullptr, w2, 1);
    k_spmm<<<dim3(T_, M_ / 4), 128>>>(b2);
    k_gemm_qkv<<<dim3(T_, M_ / 64), 256, QKV_SMEM>>>(qw, kw, vw);
    k_attn<<<dim3(T_, M_ / QT), 256, ATTN_SMEM>>>();
    cudaMemsetAsync(d_out, 0, (size_t)out_size * sizeof(float));
    k_out2<<<dim3(T_, M_ / 64), 256>>>((float*)d_out);
}